// round 1
// baseline (speedup 1.0000x reference)
#include <cuda_runtime.h>
#include <math.h>
#include <stddef.h>

// Problem constants
#define B_SZ   4
#define S_SZ   1024
#define D_M    1024
#define H_N    16
#define D_INT  64
#define D_V    128      // 2*D_INT
#define HID    4096
#define NTOK   4096     // B*S
#define HB     64       // H*B
#define LAMBDA_INIT 0.3555090675909693f
#define HEADLN_SCALE 0.6444909324090307f   // 1 - LAMBDA_INIT
#define R2_ELEMS 4194304                    // B*S*D_M
#define FULL_ELEMS 71303168                 // R2 + H*B*S*S

// ---------------- scratch (static device memory; no allocation) -------------
__device__ float g_Q[(size_t)NTOK * (H_N * D_INT)];          // [tok][h*64+e]
__device__ float g_Kb[(size_t)NTOK * (H_N * D_INT)];
__device__ float g_V[(size_t)NTOK * (H_N * D_V)];            // [tok][h*128+v]
__device__ float g_S[(size_t)HB * S_SZ * S_SZ];              // scores / A scratch
__device__ float g_O[(size_t)HB * S_SZ * D_V];               // [hb][s][v]
__device__ float g_Ocat[(size_t)NTOK * (H_N * D_V)];         // [tok][h*128+v]
__device__ float g_h1pre[(size_t)NTOK * D_M];
__device__ float g_h1[(size_t)NTOK * D_M];
__device__ float g_ffh[(size_t)NTOK * HID];
__device__ float g_r2pre[(size_t)NTOK * D_M];
__device__ float g_lamscale;                                  // 1 - lambda

// ---------------- lambda ----------------------------------------------------
__global__ void lam_kernel(const float* __restrict__ lq1, const float* __restrict__ lk1,
                           const float* __restrict__ lq2, const float* __restrict__ lk2)
{
    __shared__ float s1[64], s2[64];
    int t = threadIdx.x;
    s1[t] = lq1[t] * lk1[t];
    s2[t] = lq2[t] * lk2[t];
    __syncthreads();
    if (t == 0) {
        float d1 = 0.f, d2 = 0.f;
        for (int i = 0; i < 64; i++) { d1 += s1[i]; d2 += s2[i]; }
        float lam = expf(d1) - expf(d2) + LAMBDA_INIT;
        g_lamscale = 1.0f - lam;
    }
}

// ---------------- generic GEMM: C = A[M,K] @ B + bias + res, optional relu --
// B element (k, n) lives at Bm[(n/dout)*K*dout + k*dout + (n%dout)]
// (dout==N -> plain row-major [K,N]; dout=64/128 -> per-head stacked weights)
__global__ void __launch_bounds__(256) gemm128(
    const float* __restrict__ A, const float* __restrict__ Bm,
    const float* __restrict__ bias, const float* __restrict__ res,
    float* __restrict__ C, int M, int N, int K, int dout, int relu)
{
    __shared__ float As[16][129];
    __shared__ float Bs[16][129];
    const int tid = threadIdx.x;
    const int tx = tid & 15, ty = tid >> 4;
    const int m0 = blockIdx.y * 128, n0 = blockIdx.x * 128;

    // B column precompute (column fixed per thread across k-tiles)
    const int nn = tid & 127;
    const int n  = n0 + nn;
    const int kb = tid >> 7;                    // 0 or 1
    const int hsel = n / dout;
    const size_t colbase = (size_t)hsel * (size_t)K * (size_t)dout + (size_t)(n - hsel * dout);

    // A load slots
    const int ka = tid & 15;
    const int mrow0 = tid >> 4;

    float acc[8][8];
#pragma unroll
    for (int i = 0; i < 8; i++)
#pragma unroll
        for (int j = 0; j < 8; j++) acc[i][j] = 0.f;

    for (int k0 = 0; k0 < K; k0 += 16) {
#pragma unroll
        for (int i = 0; i < 8; i++) {
            int mm = mrow0 + i * 16;
            As[ka][mm] = A[(size_t)(m0 + mm) * K + k0 + ka];
        }
#pragma unroll
        for (int i = 0; i < 8; i++) {
            int kk = kb + 2 * i;
            Bs[kk][nn] = Bm[colbase + (size_t)(k0 + kk) * dout];
        }
        __syncthreads();
#pragma unroll
        for (int kk = 0; kk < 16; kk++) {
            float a[8], bb[8];
#pragma unroll
            for (int i = 0; i < 4; i++) { a[i] = As[kk][ty * 4 + i]; a[i + 4] = As[kk][64 + ty * 4 + i]; }
#pragma unroll
            for (int j = 0; j < 4; j++) { bb[j] = Bs[kk][tx * 4 + j]; bb[j + 4] = Bs[kk][64 + tx * 4 + j]; }
#pragma unroll
            for (int i = 0; i < 8; i++)
#pragma unroll
                for (int j = 0; j < 8; j++)
                    acc[i][j] = fmaf(a[i], bb[j], acc[i][j]);
        }
        __syncthreads();
    }

#pragma unroll
    for (int i = 0; i < 8; i++) {
        int r = m0 + ((i < 4) ? ty * 4 + i : 64 + ty * 4 + (i - 4));
#pragma unroll
        for (int j = 0; j < 8; j++) {
            int c = n0 + ((j < 4) ? tx * 4 + j : 64 + tx * 4 + (j - 4));
            float v = acc[i][j];
            if (bias) v += bias[c];
            if (res)  v += res[(size_t)r * N + c];
            if (relu) v = fmaxf(v, 0.f);
            C[(size_t)r * N + c] = v;
        }
    }
}

// ---------------- batched scores: S[z,s,t] = Q . K / 32 ---------------------
// grid (8, 8, 64), z = h*4 + b
__global__ void __launch_bounds__(256) scores128(
    const float* __restrict__ Q, const float* __restrict__ Kp, float* __restrict__ Sc)
{
    __shared__ float Qs[32][129];   // [e][s]
    __shared__ float Ks[32][129];   // [e][t]
    const int tid = threadIdx.x;
    const int tx = tid & 15, ty = tid >> 4;
    const int z = blockIdx.z, h = z >> 2, b = z & 3;
    const int s0 = blockIdx.y * 128, t0 = blockIdx.x * 128;

    float acc[8][8];
#pragma unroll
    for (int i = 0; i < 8; i++)
#pragma unroll
        for (int j = 0; j < 8; j++) acc[i][j] = 0.f;

    const int el = tid & 31;
    const int r0 = tid >> 5;

    for (int e0 = 0; e0 < 64; e0 += 32) {
#pragma unroll
        for (int i = 0; i < 16; i++) {
            int r = r0 + i * 8;
            Qs[el][r] = Q [(size_t)(b * S_SZ + s0 + r) * 1024 + h * 64 + e0 + el];
            Ks[el][r] = Kp[(size_t)(b * S_SZ + t0 + r) * 1024 + h * 64 + e0 + el];
        }
        __syncthreads();
#pragma unroll
        for (int kk = 0; kk < 32; kk++) {
            float a[8], bb[8];
#pragma unroll
            for (int i = 0; i < 4; i++) { a[i] = Qs[kk][ty * 4 + i]; a[i + 4] = Qs[kk][64 + ty * 4 + i]; }
#pragma unroll
            for (int j = 0; j < 4; j++) { bb[j] = Ks[kk][tx * 4 + j]; bb[j + 4] = Ks[kk][64 + tx * 4 + j]; }
#pragma unroll
            for (int i = 0; i < 8; i++)
#pragma unroll
                for (int j = 0; j < 8; j++)
                    acc[i][j] = fmaf(a[i], bb[j], acc[i][j]);
        }
        __syncthreads();
    }

    const float scal = 0.03125f;   // 1/sqrt(1024)
#pragma unroll
    for (int i = 0; i < 8; i++) {
        int s = s0 + ((i < 4) ? ty * 4 + i : 64 + ty * 4 + (i - 4));
#pragma unroll
        for (int j = 0; j < 8; j++) {
            int t = t0 + ((j < 4) ? tx * 4 + j : 64 + tx * 4 + (j - 4));
            Sc[((size_t)z * S_SZ + s) * S_SZ + t] = acc[i][j] * scal;
        }
    }
}

// ---------------- softmax over t, scaled by (1-lambda) ----------------------
// one block per (hb, s) row
__global__ void __launch_bounds__(256) softmax_row(
    const float* __restrict__ Sc, const int* __restrict__ mask, float* __restrict__ Aout)
{
    __shared__ float red[8];
    __shared__ float bcast;
    size_t row = blockIdx.x;
    int b = (int)((row >> 10) & 3);
    const float* in = Sc + row * 1024;
    const int* mrow = mask + b * 1024;
    int t = threadIdx.x;
    int wid = t >> 5, lane = t & 31;

    float v[4];
    float mx = -INFINITY;
#pragma unroll
    for (int i = 0; i < 4; i++) {
        int c = t + i * 256;
        float val = in[c];
        if (mrow[c] == 0) val = -INFINITY;
        v[i] = val;
        mx = fmaxf(mx, val);
    }
#pragma unroll
    for (int o = 16; o; o >>= 1) mx = fmaxf(mx, __shfl_xor_sync(0xffffffffu, mx, o));
    if (lane == 0) red[wid] = mx;
    __syncthreads();
    if (t < 32) {
        float m2 = (t < 8) ? red[t] : -INFINITY;
#pragma unroll
        for (int o = 4; o; o >>= 1) m2 = fmaxf(m2, __shfl_xor_sync(0xffffffffu, m2, o));
        if (t == 0) bcast = m2;
    }
    __syncthreads();
    mx = bcast;

    float sum = 0.f;
#pragma unroll
    for (int i = 0; i < 4; i++) { v[i] = expf(v[i] - mx); sum += v[i]; }
#pragma unroll
    for (int o = 16; o; o >>= 1) sum += __shfl_xor_sync(0xffffffffu, sum, o);
    __syncthreads();
    if (lane == 0) red[wid] = sum;
    __syncthreads();
    if (t < 32) {
        float s2 = (t < 8) ? red[t] : 0.f;
#pragma unroll
        for (int o = 4; o; o >>= 1) s2 += __shfl_xor_sync(0xffffffffu, s2, o);
        if (t == 0) bcast = g_lamscale / s2;
    }
    __syncthreads();
    float sc = bcast;
#pragma unroll
    for (int i = 0; i < 4; i++)
        Aout[row * 1024 + t + i * 256] = v[i] * sc;
}

// ---------------- batched AV: O[z,s,v] = sum_t A[z,s,t] * V[b,t,h,v] --------
// grid (8, 64); N tile = 128 (full head value dim)
__global__ void __launch_bounds__(256) av128(
    const float* __restrict__ Am, const float* __restrict__ V, float* __restrict__ O)
{
    __shared__ float As_[16][129];
    __shared__ float Vs[16][129];
    const int tid = threadIdx.x;
    const int tx = tid & 15, ty = tid >> 4;
    const int z = blockIdx.y, h = z >> 2, b = z & 3;
    const int s0 = blockIdx.x * 128;

    float acc[8][8];
#pragma unroll
    for (int i = 0; i < 8; i++)
#pragma unroll
        for (int j = 0; j < 8; j++) acc[i][j] = 0.f;

    const int ka = tid & 15, mrow0 = tid >> 4;
    const int nn = tid & 127, kb = tid >> 7;

    for (int t0 = 0; t0 < 1024; t0 += 16) {
#pragma unroll
        for (int i = 0; i < 8; i++) {
            int mm = mrow0 + i * 16;
            As_[ka][mm] = Am[((size_t)z * S_SZ + s0 + mm) * 1024 + t0 + ka];
        }
#pragma unroll
        for (int i = 0; i < 8; i++) {
            int kk = kb + 2 * i;
            Vs[kk][nn] = V[(size_t)(b * S_SZ + t0 + kk) * 2048 + h * 128 + nn];
        }
        __syncthreads();
#pragma unroll
        for (int kk = 0; kk < 16; kk++) {
            float a[8], bb[8];
#pragma unroll
            for (int i = 0; i < 4; i++) { a[i] = As_[kk][ty * 4 + i]; a[i + 4] = As_[kk][64 + ty * 4 + i]; }
#pragma unroll
            for (int j = 0; j < 4; j++) { bb[j] = Vs[kk][tx * 4 + j]; bb[j + 4] = Vs[kk][64 + tx * 4 + j]; }
#pragma unroll
            for (int i = 0; i < 8; i++)
#pragma unroll
                for (int j = 0; j < 8; j++)
                    acc[i][j] = fmaf(a[i], bb[j], acc[i][j]);
        }
        __syncthreads();
    }

#pragma unroll
    for (int i = 0; i < 8; i++) {
        int s = s0 + ((i < 4) ? ty * 4 + i : 64 + ty * 4 + (i - 4));
#pragma unroll
        for (int j = 0; j < 8; j++) {
            int c = (j < 4) ? tx * 4 + j : 64 + tx * 4 + (j - 4);
            O[((size_t)z * S_SZ + s) * 128 + c] = acc[i][j];
        }
    }
}

// ---------------- per-head LayerNorm(128) + scale + concat ------------------
// one warp per (hb, s) row; 8 rows per block
__global__ void __launch_bounds__(256) headln_kernel(
    const float* __restrict__ O, const float* __restrict__ w,
    const float* __restrict__ bvec, float* __restrict__ Ocat)
{
    int gw = blockIdx.x * 8 + (threadIdx.x >> 5);
    int lane = threadIdx.x & 31;
    const float* xr = O + (size_t)gw * 128;
    float x0 = xr[lane], x1 = xr[lane + 32], x2 = xr[lane + 64], x3 = xr[lane + 96];
    float s = x0 + x1 + x2 + x3;
#pragma unroll
    for (int o = 16; o; o >>= 1) s += __shfl_xor_sync(0xffffffffu, s, o);
    float mean = s * (1.f / 128.f);
    float d0 = x0 - mean, d1 = x1 - mean, d2 = x2 - mean, d3 = x3 - mean;
    float q = d0 * d0 + d1 * d1 + d2 * d2 + d3 * d3;
#pragma unroll
    for (int o = 16; o; o >>= 1) q += __shfl_xor_sync(0xffffffffu, q, o);
    float rstd = rsqrtf(q * (1.f / 128.f) + 1e-5f);

    int z = gw >> 10, s_ = gw & 1023;
    int h = z >> 2, b = z & 3;
    size_t base = ((size_t)(b * S_SZ + s_)) * 2048 + h * 128;
    Ocat[base + lane]      = (d0 * rstd * w[lane]      + bvec[lane])      * HEADLN_SCALE;
    Ocat[base + lane + 32] = (d1 * rstd * w[lane + 32] + bvec[lane + 32]) * HEADLN_SCALE;
    Ocat[base + lane + 64] = (d2 * rstd * w[lane + 64] + bvec[lane + 64]) * HEADLN_SCALE;
    Ocat[base + lane + 96] = (d3 * rstd * w[lane + 96] + bvec[lane + 96]) * HEADLN_SCALE;
}

// ---------------- LayerNorm over 1024 ---------------------------------------
__global__ void __launch_bounds__(256) ln1024(
    const float* __restrict__ X, const float* __restrict__ w,
    const float* __restrict__ bvec, float* __restrict__ out)
{
    __shared__ float red[8];
    __shared__ float bc;
    size_t row = blockIdx.x;
    const float* xr = X + row * 1024;
    int t = threadIdx.x;
    int wid = t >> 5, lane = t & 31;

    float v[4];
    float s = 0.f;
#pragma unroll
    for (int i = 0; i < 4; i++) { v[i] = xr[t + i * 256]; s += v[i]; }
#pragma unroll
    for (int o = 16; o; o >>= 1) s += __shfl_xor_sync(0xffffffffu, s, o);
    if (lane == 0) red[wid] = s;
    __syncthreads();
    if (t < 32) {
        float s2 = (t < 8) ? red[t] : 0.f;
#pragma unroll
        for (int o = 4; o; o >>= 1) s2 += __shfl_xor_sync(0xffffffffu, s2, o);
        if (t == 0) bc = s2 * (1.f / 1024.f);
    }
    __syncthreads();
    float mean = bc;

    float q = 0.f;
#pragma unroll
    for (int i = 0; i < 4; i++) { float d = v[i] - mean; q += d * d; }
#pragma unroll
    for (int o = 16; o; o >>= 1) q += __shfl_xor_sync(0xffffffffu, q, o);
    __syncthreads();
    if (lane == 0) red[wid] = q;
    __syncthreads();
    if (t < 32) {
        float q2 = (t < 8) ? red[t] : 0.f;
#pragma unroll
        for (int o = 4; o; o >>= 1) q2 += __shfl_xor_sync(0xffffffffu, q2, o);
        if (t == 0) bc = rsqrtf(q2 * (1.f / 1024.f) + 1e-5f);
    }
    __syncthreads();
    float rstd = bc;
#pragma unroll
    for (int i = 0; i < 4; i++) {
        int c = t + i * 256;
        out[row * 1024 + c] = (v[i] - mean) * rstd * w[c] + bvec[c];
    }
}

// ---------------- host launcher ---------------------------------------------
extern "C" void kernel_launch(void* const* d_in, const int* in_sizes, int n_in,
                              void* d_out, int out_size)
{
    const float* x    = (const float*)d_in[0];
    const int*   mask = (const int*)  d_in[1];
    const float* WQ1  = (const float*)d_in[2];
    const float* bQ1  = (const float*)d_in[3];
    const float* WK1  = (const float*)d_in[4];
    const float* bK1  = (const float*)d_in[5];
    const float* WV   = (const float*)d_in[6];
    const float* bV   = (const float*)d_in[7];
    const float* lnhw = (const float*)d_in[8];
    const float* lnhb = (const float*)d_in[9];
    const float* WO   = (const float*)d_in[10];
    const float* bO   = (const float*)d_in[11];
    const float* ln1w = (const float*)d_in[12];
    const float* ln1b = (const float*)d_in[13];
    const float* ln2w = (const float*)d_in[14];
    const float* ln2b = (const float*)d_in[15];
    const float* W1   = (const float*)d_in[16];
    const float* b1   = (const float*)d_in[17];
    const float* W2   = (const float*)d_in[18];
    const float* b2   = (const float*)d_in[19];
    const float* lq1  = (const float*)d_in[20];
    const float* lk1  = (const float*)d_in[21];
    const float* lq2  = (const float*)d_in[22];
    const float* lk2  = (const float*)d_in[23];

    float* out = (float*)d_out;

    float *qp, *kp, *vp, *sp, *op, *ocat, *h1pre, *h1, *ffh, *r2pre;
    cudaGetSymbolAddress((void**)&qp,    g_Q);
    cudaGetSymbolAddress((void**)&kp,    g_Kb);
    cudaGetSymbolAddress((void**)&vp,    g_V);
    cudaGetSymbolAddress((void**)&sp,    g_S);
    cudaGetSymbolAddress((void**)&op,    g_O);
    cudaGetSymbolAddress((void**)&ocat,  g_Ocat);
    cudaGetSymbolAddress((void**)&h1pre, g_h1pre);
    cudaGetSymbolAddress((void**)&h1,    g_h1);
    cudaGetSymbolAddress((void**)&ffh,   g_ffh);
    cudaGetSymbolAddress((void**)&r2pre, g_r2pre);

    // A goes straight into d_out when the harness expects (r2, A); else scratch.
    float* A_ptr = (out_size >= FULL_ELEMS) ? (out + R2_ELEMS) : sp;

    lam_kernel<<<1, 64>>>(lq1, lk1, lq2, lk2);

    // QKV projections
    gemm128<<<dim3(8, 32),  256>>>(x, WQ1, bQ1, nullptr, qp, NTOK, 1024, 1024, 64, 0);
    gemm128<<<dim3(8, 32),  256>>>(x, WK1, bK1, nullptr, kp, NTOK, 1024, 1024, 64, 0);
    gemm128<<<dim3(16, 32), 256>>>(x, WV,  bV,  nullptr, vp, NTOK, 2048, 1024, 128, 0);

    // attention
    scores128<<<dim3(8, 8, 64), 256>>>(qp, kp, sp);
    softmax_row<<<65536, 256>>>(sp, mask, A_ptr);
    av128<<<dim3(8, 64), 256>>>(A_ptr, vp, op);
    headln_kernel<<<8192, 256>>>(op, lnhw, lnhb, ocat);

    // output projection + residual, LN1
    gemm128<<<dim3(8, 32), 256>>>(ocat, WO, bO, x, h1pre, NTOK, 1024, 2048, 1024, 0);
    ln1024<<<4096, 256>>>(h1pre, ln1w, ln1b, h1);

    // FFN + residual, LN2 -> r2 into d_out
    gemm128<<<dim3(32, 32), 256>>>(h1, W1, b1, nullptr, ffh, NTOK, 4096, 1024, 4096, 1);
    gemm128<<<dim3(8, 32),  256>>>(ffh, W2, b2, h1, r2pre, NTOK, 1024, 4096, 1024, 0);
    ln1024<<<4096, 256>>>(r2pre, ln2w, ln2b, out);
}